// round 13
// baseline (speedup 1.0000x reference)
#include <cuda_runtime.h>
#include <cuda_fp16.h>
#include <cstdint>

#define E_DIM 1024
#define T_DIM 8192

// Scratch: QKV for the 16384 dilated tokens, layout [row][384] = Q|K|V.
__device__ float g_qkv[16384 * 384];
// Gathered X as fp16 [16384][1024]
__device__ __half g_xh[16384 * 1024];
// fp16 weight hi/lo planes, rows 0-127=Wq, 128-255=Wk, 256-383=Wv
__device__ __half g_whi[384 * 1024];
__device__ __half g_wlo[384 * 1024];
// Gathered positional bias p_bias[k][o]
__device__ float g_pbias[64 * 64];
// Per-m-block completion counters (3 slabs each)
__device__ int g_ready[128];

__device__ __forceinline__ uint32_t smem_u32(const void* p) {
    uint32_t a;
    asm("{ .reg .u64 t; cvta.to.shared.u64 t, %1; cvt.u32.u64 %0, t; }" : "=r"(a) : "l"(p));
    return a;
}

#define LDSM4(r, addr) \
    asm volatile("ldmatrix.sync.aligned.m8n8.x4.shared.b16 {%0,%1,%2,%3}, [%4];" \
        : "=r"((r)[0]), "=r"((r)[1]), "=r"((r)[2]), "=r"((r)[3]) : "r"(addr))

#define MMAF16(c, a, b0, b1) \
    asm volatile("mma.sync.aligned.m16n8k16.row.col.f32.f16.f16.f32 " \
        "{%0,%1,%2,%3}, {%4,%5,%6,%7}, {%8,%9}, {%0,%1,%2,%3};" \
        : "+f"((c)[0]), "+f"((c)[1]), "+f"((c)[2]), "+f"((c)[3]) \
        : "r"((a)[0]), "r"((a)[1]), "r"((a)[2]), "r"((a)[3]), "r"(b0), "r"(b1))

__device__ __forceinline__ void cp16(uint32_t dst, const void* src) {
    asm volatile("cp.async.cg.shared.global [%0], [%1], 16;" :: "r"(dst), "l"(src));
}
#define CP_COMMIT() asm volatile("cp.async.commit_group;" ::: "memory")

// prep: gather+convert X rows to fp16; split W to fp16 hi/lo; pbias; flags.
// blocks 0..16383: X row; 16384..16767: W row; 16768: pbias + flags.
__global__ __launch_bounds__(256) void prep_kernel(
    const float* __restrict__ x,
    const float* __restrict__ Wq, const float* __restrict__ Wk,
    const float* __restrict__ Wv, const float* __restrict__ P)
{
    const int blk = blockIdx.x;
    const int t = threadIdx.x;
    if (blk < 16384) {
        int b = blk >> 12, j = (blk >> 6) & 63, l = blk & 63;
        const float4* src = reinterpret_cast<const float4*>(
            x + ((size_t)b * T_DIM + (size_t)l * 128 + j) * E_DIM);
        float4 v = src[t];
        __half2 h0 = __floats2half2_rn(v.x, v.y);
        __half2 h1 = __floats2half2_rn(v.z, v.w);
        *reinterpret_cast<uint2*>(g_xh + (size_t)blk * 1024 + t * 4) =
            make_uint2(*reinterpret_cast<uint32_t*>(&h0), *reinterpret_cast<uint32_t*>(&h1));
    } else if (blk < 16768) {
        int r = blk - 16384;
        const float* W = (r < 128) ? Wq : (r < 256) ? Wk : Wv;
        float4 v = reinterpret_cast<const float4*>(W + (size_t)(r & 127) * 1024)[t];
        __half h[4], lo[4];
        float f[4] = {v.x, v.y, v.z, v.w};
        #pragma unroll
        for (int q = 0; q < 4; q++) {
            h[q] = __float2half_rn(f[q]);
            lo[q] = __float2half_rn(f[q] - __half2float(h[q]));
        }
        *reinterpret_cast<uint2*>(g_whi + (size_t)r * 1024 + t * 4) =
            *reinterpret_cast<uint2*>(h);
        *reinterpret_cast<uint2*>(g_wlo + (size_t)r * 1024 + t * 4) =
            *reinterpret_cast<uint2*>(lo);
    } else {
        if (t < 128) g_ready[t] = 0;
        #pragma unroll
        for (int it = 0; it < 16; it++) {
            int i = t + it * 256;
            g_pbias[i] = P[(size_t)(i >> 6) * 128 * T_DIM + (size_t)(i & 63) * 128];
        }
    }
}

// ---- fused GEMM+attention kernel ----
// bids 0..383:  GEMM slab = bid%3, m-block = bid/3
// bids 384..639: attention group g = bid-384, waits g_ready[g>>1] == 3
// GEMM stage (30720B): A fp16 [128x80]@0, Bhi@10240, Blo@20480; 3 stages = 92160.
#define STG 30720

__global__ __launch_bounds__(256, 2) void fused_kernel(float* __restrict__ out)
{
    extern __shared__ char dsm[];
    const int bid = blockIdx.x;
    const int tid = threadIdx.x;

    if (bid < 384) {
        // ================= GEMM: all-cp.async feed, pure ldsm+MMA =================
        const uint32_t smem_base = smem_u32(dsm);
        const int warp = tid >> 5, lane = tid & 31;
        const int nbase = (bid % 3) * 128;
        const int m0 = (bid / 3) * 128;

        // A loader: 2 threads/row, 32B (16 fp16) each
        const int lrow = tid >> 1;
        const int seg = tid & 1;
        const __half* pA = g_xh + (size_t)(m0 + lrow) * 1024 + seg * 16;
        const uint32_t a_dst0 = lrow * 80 + seg * 32;

        // B loader: 4 threads/row, 16B each, rows +0/+64
        const int brow_sub = tid >> 2;
        const __half *bhp[2], *blp[2];
        #pragma unroll
        for (int q = 0; q < 2; q++) {
            size_t off = (size_t)(nbase + brow_sub + q * 64) * 1024 + (tid & 3) * 8;
            bhp[q] = g_whi + off;
            blp[q] = g_wlo + off;
        }
        const uint32_t b_dst0 = brow_sub * 80 + (tid & 3) * 16;

        auto issue_stage = [&](int slot, int chunk) {
            uint32_t sb = smem_base + slot * STG;
            int k0 = chunk * 32;
            cp16(sb + a_dst0, pA + k0);
            cp16(sb + a_dst0 + 16, pA + k0 + 8);
            #pragma unroll
            for (int q = 0; q < 2; q++) {
                cp16(sb + 10240 + b_dst0 + q * 5120, bhp[q] + k0);
                cp16(sb + 20480 + b_dst0 + q * 5120, blp[q] + k0);
            }
        };

        const int m_w = (warp >> 1) * 32;
        const int n_w = (warp & 1) * 64;

        float acc[2][8][4];
        #pragma unroll
        for (int i = 0; i < 2; i++)
            #pragma unroll
            for (int j = 0; j < 8; j++)
                #pragma unroll
                for (int k = 0; k < 4; k++) acc[i][j][k] = 0.f;

        issue_stage(0, 0); CP_COMMIT();
        issue_stage(1, 1); CP_COMMIT();

        for (int c = 0; c < 32; c++) {
            asm volatile("cp.async.wait_group 1;" ::: "memory");
            __syncthreads();

            const int slot = c % 3;
            const uint32_t stA = smem_base + slot * STG;
            const uint32_t stB = stA + 10240;

            #pragma unroll
            for (int kst = 0; kst < 2; kst++) {
                uint32_t ah[2][4];
                #pragma unroll
                for (int mt = 0; mt < 2; mt++) {
                    uint32_t ra = stA + (m_w + mt * 16 + (lane & 15)) * 80
                                + kst * 32 + (lane >> 4) * 16;
                    LDSM4(ah[mt], ra);
                }
                uint32_t bb[2][2][4];
                uint32_t rbs[2][2];
                #pragma unroll
                for (int nh = 0; nh < 2; nh++)
                    #pragma unroll
                    for (int q = 0; q < 2; q++) {
                        rbs[nh][q] = stB + (n_w + nh * 32 + q * 16 + (lane & 15)) * 80
                                   + kst * 32 + (lane >> 4) * 16;
                        LDSM4(bb[nh][q], rbs[nh][q]);
                    }
                // a*bh: 16 independent MMAs
                #pragma unroll
                for (int mt = 0; mt < 2; mt++)
                    #pragma unroll
                    for (int nh = 0; nh < 2; nh++)
                        #pragma unroll
                        for (int q = 0; q < 2; q++)
                            #pragma unroll
                            for (int s = 0; s < 2; s++)
                                MMAF16(acc[mt][nh * 4 + q * 2 + s], ah[mt],
                                       bb[nh][q][s], bb[nh][q][s + 2]);
                // reload b-regs with B-lo, a*bl: 16 MMAs
                #pragma unroll
                for (int nh = 0; nh < 2; nh++)
                    #pragma unroll
                    for (int q = 0; q < 2; q++)
                        LDSM4(bb[nh][q], rbs[nh][q] + 10240);
                #pragma unroll
                for (int mt = 0; mt < 2; mt++)
                    #pragma unroll
                    for (int nh = 0; nh < 2; nh++)
                        #pragma unroll
                        for (int q = 0; q < 2; q++)
                            #pragma unroll
                            for (int s = 0; s < 2; s++)
                                MMAF16(acc[mt][nh * 4 + q * 2 + s], ah[mt],
                                       bb[nh][q][s], bb[nh][q][s + 2]);
            }

            // stage chunk c+2 into slot retired at iter c-1 (barrier-protected)
            if (c < 30) issue_stage((c + 2) % 3, c + 2);
            CP_COMMIT();
        }

        #pragma unroll
        for (int mt = 0; mt < 2; mt++) {
            #pragma unroll
            for (int nt = 0; nt < 8; nt++) {
                int row0 = m0 + m_w + mt * 16 + (lane >> 2);
                int col = nbase + n_w + nt * 8 + (lane & 3) * 2;
                float* p0 = &g_qkv[(size_t)row0 * 384 + col];
                float* p1 = &g_qkv[(size_t)(row0 + 8) * 384 + col];
                *reinterpret_cast<float2*>(p0) = make_float2(acc[mt][nt][0], acc[mt][nt][1]);
                *reinterpret_cast<float2*>(p1) = make_float2(acc[mt][nt][2], acc[mt][nt][3]);
            }
        }
        __threadfence();
        __syncthreads();
        if (tid == 0) atomicAdd(&g_ready[bid / 3], 1);

    } else {
        // ================= attention part =================
        float* sm = reinterpret_cast<float*>(dsm);
        float* Kt  = sm;                  // [128][68] transposed: Kt[p][k]
        float* Vs  = Kt + 128 * 68;       // [64][128]
        float* QtS = Vs + 64 * 128;       // [128][68] Qt[p][o], overlaid by S[64][68]
        const int g = bid - 384;
        const int mb = g >> 1;
        const int bbk = g >> 6, jseg = g & 63;
        const float* base = g_qkv + (size_t)g * 64 * 384;

        if (tid == 0) {
            int v;
            do {
                asm volatile("ld.acquire.gpu.s32 %0, [%1];" : "=r"(v) : "l"(g_ready + mb));
                if (v < 3) __nanosleep(128);
            } while (v < 3);
        }
        __syncthreads();

        for (int idx = tid; idx < 64 * 32; idx += 256) {
            int row = idx >> 5;
            int c4 = (idx & 31) * 4;
            const float* rp = base + (size_t)row * 384;
            float4 qv = *reinterpret_cast<const float4*>(rp + c4);
            float4 kv = *reinterpret_cast<const float4*>(rp + 128 + c4);
            float4 vv = *reinterpret_cast<const float4*>(rp + 256 + c4);
            *reinterpret_cast<float4*>(Vs + row * 128 + c4) = vv;
            Kt[(c4 + 0) * 68 + row] = kv.x;
            Kt[(c4 + 1) * 68 + row] = kv.y;
            Kt[(c4 + 2) * 68 + row] = kv.z;
            Kt[(c4 + 3) * 68 + row] = kv.w;
            QtS[(c4 + 0) * 68 + row] = qv.x;
            QtS[(c4 + 1) * 68 + row] = qv.y;
            QtS[(c4 + 2) * 68 + row] = qv.z;
            QtS[(c4 + 3) * 68 + row] = qv.w;
        }
        __syncthreads();

        const int tk = tid >> 4, to = tid & 15;
        float4 sval[4];
        {
            float sacc[4][4];
            #pragma unroll
            for (int i = 0; i < 4; i++)
                #pragma unroll
                for (int j = 0; j < 4; j++) sacc[i][j] = 0.f;
            for (int p = 0; p < 128; p++) {
                float4 rk = *reinterpret_cast<const float4*>(Kt + p * 68 + tk * 4);
                float4 rq = *reinterpret_cast<const float4*>(QtS + p * 68 + to * 4);
                float ka[4] = {rk.x, rk.y, rk.z, rk.w};
                float qa[4] = {rq.x, rq.y, rq.z, rq.w};
                #pragma unroll
                for (int i = 0; i < 4; i++)
                    #pragma unroll
                    for (int j = 0; j < 4; j++)
                        sacc[i][j] = fmaf(ka[i], qa[j], sacc[i][j]);
            }
            const float nf = 0.08838834764831845f;  // 1/sqrt(128)
            #pragma unroll
            for (int i = 0; i < 4; i++) {
                int k = tk * 4 + i;
                float e[4];
                #pragma unroll
                for (int j = 0; j < 4; j++) {
                    int o = to * 4 + j;
                    float v = (k >= o) ? sacc[i][j] : -10000.0f;
                    v += g_pbias[k * 64 + o];
                    e[j] = v * nf;
                }
                sval[i] = make_float4(e[0], e[1], e[2], e[3]);
            }
        }
        __syncthreads();
        #pragma unroll
        for (int i = 0; i < 4; i++)
            *reinterpret_cast<float4*>(QtS + (tk * 4 + i) * 68 + to * 4) = sval[i];
        __syncthreads();

        {
            const int o = tid >> 2, seg2 = tid & 3;
            float e[16];
            float mx = -3.402823466e38f;
            #pragma unroll
            for (int i = 0; i < 16; i++) {
                e[i] = QtS[(seg2 * 16 + i) * 68 + o];
                mx = fmaxf(mx, e[i]);
            }
            mx = fmaxf(mx, __shfl_xor_sync(0xffffffffu, mx, 1));
            mx = fmaxf(mx, __shfl_xor_sync(0xffffffffu, mx, 2));
            float ssum = 0.f;
            #pragma unroll
            for (int i = 0; i < 16; i++) { e[i] = __expf(e[i] - mx); ssum += e[i]; }
            ssum += __shfl_xor_sync(0xffffffffu, ssum, 1);
            ssum += __shfl_xor_sync(0xffffffffu, ssum, 2);
            float inv = 1.0f / ssum;
            #pragma unroll
            for (int i = 0; i < 16; i++)
                QtS[(seg2 * 16 + i) * 68 + o] = e[i] * inv;
        }
        __syncthreads();

        {
            const int td = tid >> 4, tmm = tid & 15;
            float acc[4][8];
            #pragma unroll
            for (int i = 0; i < 4; i++)
                #pragma unroll
                for (int j = 0; j < 8; j++) acc[i][j] = 0.f;
            for (int k = 0; k < 64; k++) {
                float4 rs4 = *reinterpret_cast<const float4*>(QtS + k * 68 + td * 4);
                float rs[4] = {rs4.x, rs4.y, rs4.z, rs4.w};
                float4 v0 = *reinterpret_cast<const float4*>(Vs + k * 128 + tmm * 8);
                float4 v1 = *reinterpret_cast<const float4*>(Vs + k * 128 + tmm * 8 + 4);
                float rv[8] = {v0.x, v0.y, v0.z, v0.w, v1.x, v1.y, v1.z, v1.w};
                #pragma unroll
                for (int i = 0; i < 4; i++)
                    #pragma unroll
                    for (int j = 0; j < 8; j++)
                        acc[i][j] = fmaf(rs[i], rv[j], acc[i][j]);
            }
            const float4 z = make_float4(0.f, 0.f, 0.f, 0.f);
            #pragma unroll
            for (int i = 0; i < 4; i++) {
                int d = td * 4 + i;
                size_t orow = (size_t)bbk * T_DIM + 2 * ((size_t)jseg * 64 + d);
                float* op = out + orow * 128 + tmm * 8;
                *reinterpret_cast<float4*>(op)     = make_float4(acc[i][0], acc[i][1], acc[i][2], acc[i][3]);
                *reinterpret_cast<float4*>(op + 4) = make_float4(acc[i][4], acc[i][5], acc[i][6], acc[i][7]);
                float* oz = op + 128;   // odd row (poisoned) -> zero
                *reinterpret_cast<float4*>(oz)     = z;
                *reinterpret_cast<float4*>(oz + 4) = z;
            }
        }
    }
}

extern "C" void kernel_launch(void* const* d_in, const int* in_sizes, int n_in,
                              void* d_out, int out_size) {
    const float* x  = (const float*)d_in[0];   // x_in  [4, 8192, 1024]
    const float* P  = (const float*)d_in[1];   // P     [8192, 8192]
    const float* Wk = (const float*)d_in[2];   // Wk    [128, 1024]
    const float* Wq = (const float*)d_in[3];   // Wq    [128, 1024]
    const float* Wv = (const float*)d_in[4];   // Wv    [128, 1024]
    float* out = (float*)d_out;                // [4, 8192, 128] fp32

    prep_kernel<<<16769, 256>>>(x, Wq, Wk, Wv, P);

    // attn smem need: (128*68 + 64*128 + 128*68)*4 = 102400 B (> GEMM's 92160)
    int fsm = 102400;
    cudaFuncSetAttribute(fused_kernel, cudaFuncAttributeMaxDynamicSharedMemorySize, fsm);
    fused_kernel<<<640, 256, fsm>>>(out);
}

// round 15
// speedup vs baseline: 1.0041x; 1.0041x over previous
#include <cuda_runtime.h>
#include <cuda_fp16.h>
#include <cstdint>

#define E_DIM 1024
#define T_DIM 8192

// Scratch: QKV for the 16384 dilated tokens, layout [row][384] = Q|K|V.
__device__ float g_qkv[16384 * 384];
// Gathered X as fp16 [16384][1024]
__device__ __half g_xh[16384 * 1024];
// fp16 weight hi/lo planes, rows 0-127=Wq, 128-255=Wk, 256-383=Wv
__device__ __half g_whi[384 * 1024];
__device__ __half g_wlo[384 * 1024];
// Gathered positional bias p_bias[k][o]
__device__ float g_pbias[64 * 64];
// Per-m-block completion counters (3 slabs each)
__device__ int g_ready[128];

__device__ __forceinline__ uint32_t smem_u32(const void* p) {
    uint32_t a;
    asm("{ .reg .u64 t; cvta.to.shared.u64 t, %1; cvt.u32.u64 %0, t; }" : "=r"(a) : "l"(p));
    return a;
}

#define LDSM4(r, addr) \
    asm volatile("ldmatrix.sync.aligned.m8n8.x4.shared.b16 {%0,%1,%2,%3}, [%4];" \
        : "=r"((r)[0]), "=r"((r)[1]), "=r"((r)[2]), "=r"((r)[3]) : "r"(addr))

#define MMAF16(c, a, b0, b1) \
    asm volatile("mma.sync.aligned.m16n8k16.row.col.f32.f16.f16.f32 " \
        "{%0,%1,%2,%3}, {%4,%5,%6,%7}, {%8,%9}, {%0,%1,%2,%3};" \
        : "+f"((c)[0]), "+f"((c)[1]), "+f"((c)[2]), "+f"((c)[3]) \
        : "r"((a)[0]), "r"((a)[1]), "r"((a)[2]), "r"((a)[3]), "r"(b0), "r"(b1))

__device__ __forceinline__ void cp16(uint32_t dst, const void* src) {
    asm volatile("cp.async.cg.shared.global [%0], [%1], 16;" :: "r"(dst), "l"(src));
}
#define CP_COMMIT() asm volatile("cp.async.commit_group;" ::: "memory")

// prep: gather+convert X to fp16 (locality-ordered); split W; pbias; flags.
// blocks 0..255: (b,l) pair (b=blk>>6, l=blk&63) — 64 consecutive x tokens.
// blocks 256..639: one W row each; block 640: pbias + flags.
__global__ __launch_bounds__(256) void prep_kernel(
    const float* __restrict__ x,
    const float* __restrict__ Wq, const float* __restrict__ Wk,
    const float* __restrict__ Wv, const float* __restrict__ P)
{
    const int blk = blockIdx.x;
    const int t = threadIdx.x;
    if (blk < 256) {
        const int b = blk >> 6, l = blk & 63;
        // iteration j: all 256 threads convert token l*128+j -> row b*4096 + j*64 + l
        const float4* src = reinterpret_cast<const float4*>(
            x + ((size_t)b * T_DIM + (size_t)l * 128) * E_DIM);
        #pragma unroll 4
        for (int j = 0; j < 64; j++) {
            float4 v = src[j * 256 + t];
            __half2 h0 = __floats2half2_rn(v.x, v.y);
            __half2 h1 = __floats2half2_rn(v.z, v.w);
            size_t r = (size_t)b * 4096 + (size_t)j * 64 + l;
            *reinterpret_cast<uint2*>(g_xh + r * 1024 + t * 4) =
                make_uint2(*reinterpret_cast<uint32_t*>(&h0), *reinterpret_cast<uint32_t*>(&h1));
        }
    } else if (blk < 640) {
        int r = blk - 256;
        const float* W = (r < 128) ? Wq : (r < 256) ? Wk : Wv;
        float4 v = reinterpret_cast<const float4*>(W + (size_t)(r & 127) * 1024)[t];
        __half h[4], lo[4];
        float f[4] = {v.x, v.y, v.z, v.w};
        #pragma unroll
        for (int q = 0; q < 4; q++) {
            h[q] = __float2half_rn(f[q]);
            lo[q] = __float2half_rn(f[q] - __half2float(h[q]));
        }
        *reinterpret_cast<uint2*>(g_whi + (size_t)r * 1024 + t * 4) =
            *reinterpret_cast<uint2*>(h);
        *reinterpret_cast<uint2*>(g_wlo + (size_t)r * 1024 + t * 4) =
            *reinterpret_cast<uint2*>(lo);
    } else {
        if (t < 128) g_ready[t] = 0;
        #pragma unroll
        for (int it = 0; it < 16; it++) {
            int i = t + it * 256;
            g_pbias[i] = P[(size_t)(i >> 6) * 128 * T_DIM + (size_t)(i & 63) * 128];
        }
    }
}

// ---- fused GEMM+attention kernel ----
// bids 0..383:  GEMM slab = bid%3, m-block = bid/3
// bids 384..639: attention group g = bid-384, waits g_ready[g>>1] == 3
// GEMM stage (30720B): A fp16 [128x80]@0, Bhi@10240, Blo@20480; 3 stages = 92160.
#define STG 30720

__global__ __launch_bounds__(256, 2) void fused_kernel(float* __restrict__ out)
{
    extern __shared__ char dsm[];
    const int bid = blockIdx.x;
    const int tid = threadIdx.x;

    if (bid < 384) {
        // ================= GEMM: all-cp.async feed, pure ldsm+MMA =================
        const uint32_t smem_base = smem_u32(dsm);
        const int warp = tid >> 5, lane = tid & 31;
        const int nbase = (bid % 3) * 128;
        const int m0 = (bid / 3) * 128;

        // A loader: 2 threads/row, 32B (16 fp16) each
        const int lrow = tid >> 1;
        const int seg = tid & 1;
        const __half* pA = g_xh + (size_t)(m0 + lrow) * 1024 + seg * 16;
        const uint32_t a_dst0 = lrow * 80 + seg * 32;

        // B loader: 4 threads/row, 16B each, rows +0/+64
        const int brow_sub = tid >> 2;
        const __half *bhp[2], *blp[2];
        #pragma unroll
        for (int q = 0; q < 2; q++) {
            size_t off = (size_t)(nbase + brow_sub + q * 64) * 1024 + (tid & 3) * 8;
            bhp[q] = g_whi + off;
            blp[q] = g_wlo + off;
        }
        const uint32_t b_dst0 = brow_sub * 80 + (tid & 3) * 16;

        auto issue_stage = [&](int slot, int chunk) {
            uint32_t sb = smem_base + slot * STG;
            int k0 = chunk * 32;
            cp16(sb + a_dst0, pA + k0);
            cp16(sb + a_dst0 + 16, pA + k0 + 8);
            #pragma unroll
            for (int q = 0; q < 2; q++) {
                cp16(sb + 10240 + b_dst0 + q * 5120, bhp[q] + k0);
                cp16(sb + 20480 + b_dst0 + q * 5120, blp[q] + k0);
            }
        };

        const int m_w = (warp >> 1) * 32;
        const int n_w = (warp & 1) * 64;

        float acc[2][8][4];
        #pragma unroll
        for (int i = 0; i < 2; i++)
            #pragma unroll
            for (int j = 0; j < 8; j++)
                #pragma unroll
                for (int k = 0; k < 4; k++) acc[i][j][k] = 0.f;

        issue_stage(0, 0); CP_COMMIT();
        issue_stage(1, 1); CP_COMMIT();

        for (int c = 0; c < 32; c++) {
            asm volatile("cp.async.wait_group 1;" ::: "memory");
            __syncthreads();

            const int slot = c % 3;
            const uint32_t stA = smem_base + slot * STG;
            const uint32_t stB = stA + 10240;

            #pragma unroll
            for (int kst = 0; kst < 2; kst++) {
                uint32_t ah[2][4];
                #pragma unroll
                for (int mt = 0; mt < 2; mt++) {
                    uint32_t ra = stA + (m_w + mt * 16 + (lane & 15)) * 80
                                + kst * 32 + (lane >> 4) * 16;
                    LDSM4(ah[mt], ra);
                }
                uint32_t bb[2][2][4];
                uint32_t rbs[2][2];
                #pragma unroll
                for (int nh = 0; nh < 2; nh++)
                    #pragma unroll
                    for (int q = 0; q < 2; q++) {
                        rbs[nh][q] = stB + (n_w + nh * 32 + q * 16 + (lane & 15)) * 80
                                   + kst * 32 + (lane >> 4) * 16;
                        LDSM4(bb[nh][q], rbs[nh][q]);
                    }
                // a*bh: 16 independent MMAs
                #pragma unroll
                for (int mt = 0; mt < 2; mt++)
                    #pragma unroll
                    for (int nh = 0; nh < 2; nh++)
                        #pragma unroll
                        for (int q = 0; q < 2; q++)
                            #pragma unroll
                            for (int s = 0; s < 2; s++)
                                MMAF16(acc[mt][nh * 4 + q * 2 + s], ah[mt],
                                       bb[nh][q][s], bb[nh][q][s + 2]);
                // reload b-regs with B-lo, a*bl: 16 MMAs
                #pragma unroll
                for (int nh = 0; nh < 2; nh++)
                    #pragma unroll
                    for (int q = 0; q < 2; q++)
                        LDSM4(bb[nh][q], rbs[nh][q] + 10240);
                #pragma unroll
                for (int mt = 0; mt < 2; mt++)
                    #pragma unroll
                    for (int nh = 0; nh < 2; nh++)
                        #pragma unroll
                        for (int q = 0; q < 2; q++)
                            #pragma unroll
                            for (int s = 0; s < 2; s++)
                                MMAF16(acc[mt][nh * 4 + q * 2 + s], ah[mt],
                                       bb[nh][q][s], bb[nh][q][s + 2]);
            }

            // stage chunk c+2 into slot retired at iter c-1 (barrier-protected)
            if (c < 30) issue_stage((c + 2) % 3, c + 2);
            CP_COMMIT();
        }

        #pragma unroll
        for (int mt = 0; mt < 2; mt++) {
            #pragma unroll
            for (int nt = 0; nt < 8; nt++) {
                int row0 = m0 + m_w + mt * 16 + (lane >> 2);
                int col = nbase + n_w + nt * 8 + (lane & 3) * 2;
                float* p0 = &g_qkv[(size_t)row0 * 384 + col];
                float* p1 = &g_qkv[(size_t)(row0 + 8) * 384 + col];
                *reinterpret_cast<float2*>(p0) = make_float2(acc[mt][nt][0], acc[mt][nt][1]);
                *reinterpret_cast<float2*>(p1) = make_float2(acc[mt][nt][2], acc[mt][nt][3]);
            }
        }
        __threadfence();
        __syncthreads();
        if (tid == 0) atomicAdd(&g_ready[bid / 3], 1);

    } else {
        // ================= attention part =================
        float* sm = reinterpret_cast<float*>(dsm);
        float* Kt  = sm;                  // [128][68] transposed: Kt[p][k]
        float* Vs  = Kt + 128 * 68;       // [64][128]
        float* QtS = Vs + 64 * 128;       // [128][68] Qt[p][o], overlaid by S[64][68]
        const int g = bid - 384;
        const int mb = g >> 1;
        const int bbk = g >> 6, jseg = g & 63;
        const float* base = g_qkv + (size_t)g * 64 * 384;

        if (tid == 0) {
            int v;
            do {
                asm volatile("ld.acquire.gpu.s32 %0, [%1];" : "=r"(v) : "l"(g_ready + mb));
                if (v < 3) __nanosleep(128);
            } while (v < 3);
        }
        __syncthreads();

        for (int idx = tid; idx < 64 * 32; idx += 256) {
            int row = idx >> 5;
            int c4 = (idx & 31) * 4;
            const float* rp = base + (size_t)row * 384;
            float4 qv = *reinterpret_cast<const float4*>(rp + c4);
            float4 kv = *reinterpret_cast<const float4*>(rp + 128 + c4);
            float4 vv = *reinterpret_cast<const float4*>(rp + 256 + c4);
            *reinterpret_cast<float4*>(Vs + row * 128 + c4) = vv;
            Kt[(c4 + 0) * 68 + row] = kv.x;
            Kt[(c4 + 1) * 68 + row] = kv.y;
            Kt[(c4 + 2) * 68 + row] = kv.z;
            Kt[(c4 + 3) * 68 + row] = kv.w;
            QtS[(c4 + 0) * 68 + row] = qv.x;
            QtS[(c4 + 1) * 68 + row] = qv.y;
            QtS[(c4 + 2) * 68 + row] = qv.z;
            QtS[(c4 + 3) * 68 + row] = qv.w;
        }
        __syncthreads();

        const int tk = tid >> 4, to = tid & 15;
        float4 sval[4];
        {
            float sacc[4][4];
            #pragma unroll
            for (int i = 0; i < 4; i++)
                #pragma unroll
                for (int j = 0; j < 4; j++) sacc[i][j] = 0.f;
            for (int p = 0; p < 128; p++) {
                float4 rk = *reinterpret_cast<const float4*>(Kt + p * 68 + tk * 4);
                float4 rq = *reinterpret_cast<const float4*>(QtS + p * 68 + to * 4);
                float ka[4] = {rk.x, rk.y, rk.z, rk.w};
                float qa[4] = {rq.x, rq.y, rq.z, rq.w};
                #pragma unroll
                for (int i = 0; i < 4; i++)
                    #pragma unroll
                    for (int j = 0; j < 4; j++)
                        sacc[i][j] = fmaf(ka[i], qa[j], sacc[i][j]);
            }
            const float nf = 0.08838834764831845f;  // 1/sqrt(128)
            #pragma unroll
            for (int i = 0; i < 4; i++) {
                int k = tk * 4 + i;
                float e[4];
                #pragma unroll
                for (int j = 0; j < 4; j++) {
                    int o = to * 4 + j;
                    float v = (k >= o) ? sacc[i][j] : -10000.0f;
                    v += g_pbias[k * 64 + o];
                    e[j] = v * nf;
                }
                sval[i] = make_float4(e[0], e[1], e[2], e[3]);
            }
        }
        __syncthreads();
        #pragma unroll
        for (int i = 0; i < 4; i++)
            *reinterpret_cast<float4*>(QtS + (tk * 4 + i) * 68 + to * 4) = sval[i];
        __syncthreads();

        {
            const int o = tid >> 2, seg2 = tid & 3;
            float e[16];
            float mx = -3.402823466e38f;
            #pragma unroll
            for (int i = 0; i < 16; i++) {
                e[i] = QtS[(seg2 * 16 + i) * 68 + o];
                mx = fmaxf(mx, e[i]);
            }
            mx = fmaxf(mx, __shfl_xor_sync(0xffffffffu, mx, 1));
            mx = fmaxf(mx, __shfl_xor_sync(0xffffffffu, mx, 2));
            float ssum = 0.f;
            #pragma unroll
            for (int i = 0; i < 16; i++) { e[i] = __expf(e[i] - mx); ssum += e[i]; }
            ssum += __shfl_xor_sync(0xffffffffu, ssum, 1);
            ssum += __shfl_xor_sync(0xffffffffu, ssum, 2);
            float inv = 1.0f / ssum;
            #pragma unroll
            for (int i = 0; i < 16; i++)
                QtS[(seg2 * 16 + i) * 68 + o] = e[i] * inv;
        }
        __syncthreads();

        {
            const int td = tid >> 4, tmm = tid & 15;
            float acc[4][8];
            #pragma unroll
            for (int i = 0; i < 4; i++)
                #pragma unroll
                for (int j = 0; j < 8; j++) acc[i][j] = 0.f;
            for (int k = 0; k < 64; k++) {
                float4 rs4 = *reinterpret_cast<const float4*>(QtS + k * 68 + td * 4);
                float rs[4] = {rs4.x, rs4.y, rs4.z, rs4.w};
                float4 v0 = *reinterpret_cast<const float4*>(Vs + k * 128 + tmm * 8);
                float4 v1 = *reinterpret_cast<const float4*>(Vs + k * 128 + tmm * 8 + 4);
                float rv[8] = {v0.x, v0.y, v0.z, v0.w, v1.x, v1.y, v1.z, v1.w};
                #pragma unroll
                for (int i = 0; i < 4; i++)
                    #pragma unroll
                    for (int j = 0; j < 8; j++)
                        acc[i][j] = fmaf(rs[i], rv[j], acc[i][j]);
            }
            const float4 z = make_float4(0.f, 0.f, 0.f, 0.f);
            #pragma unroll
            for (int i = 0; i < 4; i++) {
                int d = td * 4 + i;
                size_t orow = (size_t)bbk * T_DIM + 2 * ((size_t)jseg * 64 + d);
                float* op = out + orow * 128 + tmm * 8;
                *reinterpret_cast<float4*>(op)     = make_float4(acc[i][0], acc[i][1], acc[i][2], acc[i][3]);
                *reinterpret_cast<float4*>(op + 4) = make_float4(acc[i][4], acc[i][5], acc[i][6], acc[i][7]);
                float* oz = op + 128;   // odd row (poisoned) -> zero
                *reinterpret_cast<float4*>(oz)     = z;
                *reinterpret_cast<float4*>(oz + 4) = z;
            }
        }
    }
}

extern "C" void kernel_launch(void* const* d_in, const int* in_sizes, int n_in,
                              void* d_out, int out_size) {
    const float* x  = (const float*)d_in[0];   // x_in  [4, 8192, 1024]
    const float* P  = (const float*)d_in[1];   // P     [8192, 8192]
    const float* Wk = (const float*)d_in[2];   // Wk    [128, 1024]
    const float* Wq = (const float*)d_in[3];   // Wq    [128, 1024]
    const float* Wv = (const float*)d_in[4];   // Wv    [128, 1024]
    float* out = (float*)d_out;                // [4, 8192, 128] fp32

    prep_kernel<<<641, 256>>>(x, Wq, Wk, Wv, P);

    // attn smem need: (128*68 + 64*128 + 128*68)*4 = 102400 B (> GEMM's 92160)
    int fsm = 102400;
    cudaFuncSetAttribute(fused_kernel, cudaFuncAttributeMaxDynamicSharedMemorySize, fsm);
    fused_kernel<<<640, 256, fsm>>>(out);
}